// round 3
// baseline (speedup 1.0000x reference)
#include <cuda_runtime.h>
#include <math.h>

#define NTOK 196
#define EMBD 256
#define HIDD 1024
#define NH   8
#define DHD  32

// ---------------- scratch (allocation-free: __device__ globals) ----------------
__device__ float g_qkv[2][NTOK * 768];    // per-stream QKV projection (n, (h d 3))
__device__ float g_nrm1[2][NTOK * EMBD];  // LN1 outputs (residual base)
__device__ float g_attn[2][NTOK * EMBD];  // attention output, (n, h*d)
__device__ float g_r[2][NTOK * EMBD];     // residual sum
__device__ float g_l[2][NTOK * EMBD];     // LN2 outputs
__device__ float g_hid[2][NTOK * HIDD];   // FF hidden
__device__ float g_o[2][NTOK * EMBD];     // final per-stream output

// ---------------- LayerNorm: one block per (row, stream) ----------------
__global__ void ln_kernel(const float* __restrict__ x0, const float* __restrict__ x1,
                          const float* __restrict__ w0, const float* __restrict__ b0,
                          const float* __restrict__ w1, const float* __restrict__ b1,
                          float* __restrict__ o0, float* __restrict__ o1)
{
    int s = blockIdx.y;
    const float* x = (s ? x1 : x0) + blockIdx.x * EMBD;
    const float* w = s ? w1 : w0;
    const float* b = s ? b1 : b0;
    float* o = (s ? o1 : o0) + blockIdx.x * EMBD;

    int tid = threadIdx.x;          // 256 threads, one element each
    float v = x[tid];

    __shared__ float red[8];
    float t = v;
    #pragma unroll
    for (int off = 16; off; off >>= 1) t += __shfl_xor_sync(0xffffffffu, t, off);
    if ((tid & 31) == 0) red[tid >> 5] = t;
    __syncthreads();
    float mean = (red[0] + red[1] + red[2] + red[3] +
                  red[4] + red[5] + red[6] + red[7]) * (1.0f / EMBD);
    __syncthreads();

    float d = v - mean;
    t = d * d;
    #pragma unroll
    for (int off = 16; off; off >>= 1) t += __shfl_xor_sync(0xffffffffu, t, off);
    if ((tid & 31) == 0) red[tid >> 5] = t;
    __syncthreads();
    float var = (red[0] + red[1] + red[2] + red[3] +
                 red[4] + red[5] + red[6] + red[7]) * (1.0f / EMBD);

    o[tid] = d * rsqrtf(var + 1e-5f) * w[tid] + b[tid];
}

// ---------------- generic tiled SGEMM with fused epilogue ----------------
// C[M,N] = act(A[M,K] @ B[K,N] + bias[N]) (+ res[M,N])
// act: 0 = none, 1 = exact GELU (applied before residual, matching FF order)
__global__ void sgemm(const float* __restrict__ A, const float* __restrict__ B,
                      const float* __restrict__ bias, const float* __restrict__ res,
                      float* __restrict__ C, int M, int N, int K, int act)
{
    __shared__ float As[32][33];
    __shared__ float Bs[32][33];

    int tx = threadIdx.x, ty = threadIdx.y;          // 16x16
    int tid = ty * 16 + tx;
    int row0 = blockIdx.y * 32, col0 = blockIdx.x * 32;

    float acc00 = 0.f, acc01 = 0.f, acc10 = 0.f, acc11 = 0.f;

    for (int k0 = 0; k0 < K; k0 += 32) {
        // N and K are multiples of 32 for all calls; only M (=196) is ragged.
        #pragma unroll
        for (int i = tid; i < 1024; i += 256) {
            int r = i >> 5, c = i & 31;
            As[r][c] = (row0 + r < M) ? A[(row0 + r) * K + k0 + c] : 0.f;
            Bs[r][c] = B[(k0 + r) * N + col0 + c];
        }
        __syncthreads();
        #pragma unroll
        for (int k = 0; k < 32; k++) {
            float a0 = As[ty][k], a1 = As[ty + 16][k];
            float b0 = Bs[k][tx], b1 = Bs[k][tx + 16];
            acc00 += a0 * b0; acc01 += a0 * b1;
            acc10 += a1 * b0; acc11 += a1 * b1;
        }
        __syncthreads();
    }

    int r0 = row0 + ty, r1 = row0 + ty + 16;
    int c0 = col0 + tx, c1 = col0 + tx + 16;
    float bi0 = bias[c0], bi1 = bias[c1];

    float v;
    #define EPI(acc, rr, cc, bi)                                              \
        if ((rr) < M) {                                                       \
            v = (acc) + (bi);                                                 \
            if (act) v = 0.5f * v * (1.0f + erff(v * 0.70710678118654752f));  \
            if (res) v += res[(rr) * N + (cc)];                               \
            C[(rr) * N + (cc)] = v;                                           \
        }
    EPI(acc00, r0, c0, bi0)
    EPI(acc01, r0, c1, bi1)
    EPI(acc10, r1, c0, bi0)
    EPI(acc11, r1, c1, bi1)
    #undef EPI
}

// ---------------- attention: one block per (query n, head h, out-stream s) ----
// Q from stream s, K/V from stream 1-s (cross attention). 128 threads.
__global__ void attn_kernel()
{
    int n = blockIdx.x, h = blockIdx.y, s = blockIdx.z;
    const float* qkv_q  = g_qkv[s];
    const float* qkv_kv = g_qkv[1 - s];

    __shared__ float qs[DHD];
    __shared__ float p[NTOK];
    __shared__ float red[4];
    __shared__ float outp[4][DHD];

    int tid = threadIdx.x;

    if (tid < DHD) qs[tid] = qkv_q[n * 768 + (h * DHD + tid) * 3 + 0];
    __syncthreads();

    // scores
    float lmax = -1e30f;
    for (int j = tid; j < NTOK; j += 128) {
        const float* kr = qkv_kv + j * 768 + h * DHD * 3 + 1;
        float d = 0.f;
        #pragma unroll
        for (int dd = 0; dd < DHD; dd++) d += qs[dd] * kr[dd * 3];
        d *= (1.0f / 16.0f);
        p[j] = d;
        lmax = fmaxf(lmax, d);
    }
    #pragma unroll
    for (int off = 16; off; off >>= 1) lmax = fmaxf(lmax, __shfl_xor_sync(0xffffffffu, lmax, off));
    if ((tid & 31) == 0) red[tid >> 5] = lmax;
    __syncthreads();
    float mx = fmaxf(fmaxf(red[0], red[1]), fmaxf(red[2], red[3]));
    __syncthreads();

    // exp + sum
    float lsum = 0.f;
    for (int j = tid; j < NTOK; j += 128) {
        float e = __expf(p[j] - mx);
        p[j] = e;
        lsum += e;
    }
    #pragma unroll
    for (int off = 16; off; off >>= 1) lsum += __shfl_xor_sync(0xffffffffu, lsum, off);
    __syncthreads();                 // all p[] writes visible; safe to reuse red
    if ((tid & 31) == 0) red[tid >> 5] = lsum;
    __syncthreads();
    float inv = 1.0f / (red[0] + red[1] + red[2] + red[3]);

    // out[d] = inv * sum_j p[j] * V[j][d]; 4 partial chunks of 49 per d
    int d = tid & 31, part = tid >> 5;
    float o = 0.f;
    int j0 = part * 49, j1 = j0 + 49;
    for (int j = j0; j < j1; j++)
        o += p[j] * qkv_kv[j * 768 + (h * DHD + d) * 3 + 2];
    outp[part][d] = o;
    __syncthreads();
    if (part == 0)
        g_attn[s][n * EMBD + h * DHD + d] =
            (outp[0][d] + outp[1][d] + outp[2][d] + outp[3][d]) * inv;
}

// ---------------- pixel-shuffle recon + channel concat ----------------
// out (1,2,224,224): ch0 = ir path (stream 1), ch1 = vis path (stream 0)
__global__ void recon_kernel(float* __restrict__ out)
{
    int t = blockIdx.x * 256 + threadIdx.x;
    if (t >= 2 * 224 * 224) return;
    int ch = t / (224 * 224);
    int f = t % (224 * 224);
    int j = f % 14; f /= 14;
    int i = f % 14; f /= 14;
    int q = f % 16;
    int pp = f / 16;
    int src = (ch == 0) ? 1 : 0;
    out[t] = g_o[src][(i * 14 + j) * EMBD + pp * 16 + q];
}

// ---------------- launch ----------------
extern "C" void kernel_launch(void* const* d_in, const int* in_sizes, int n_in,
                              void* d_out, int out_size)
{
    const float* vis    = (const float*)d_in[0];
    const float* ir     = (const float*)d_in[1];
    const float* ln1v_w = (const float*)d_in[2];
    const float* ln1v_b = (const float*)d_in[3];
    const float* ln1i_w = (const float*)d_in[4];
    const float* ln1i_b = (const float*)d_in[5];
    const float* ln2v_w = (const float*)d_in[6];
    const float* ln2v_b = (const float*)d_in[7];
    const float* ln2i_w = (const float*)d_in[8];
    const float* ln2i_b = (const float*)d_in[9];
    const float* Wqkv_v = (const float*)d_in[10];
    const float* bqkv_v = (const float*)d_in[11];
    const float* Wqkv_i = (const float*)d_in[12];
    const float* bqkv_i = (const float*)d_in[13];
    const float* Wp_v   = (const float*)d_in[14];
    const float* bp_v   = (const float*)d_in[15];
    const float* Wp_i   = (const float*)d_in[16];
    const float* bp_i   = (const float*)d_in[17];
    const float* W1v    = (const float*)d_in[18];
    const float* b1v    = (const float*)d_in[19];
    const float* W2v    = (const float*)d_in[20];
    const float* b2v    = (const float*)d_in[21];
    const float* W1i    = (const float*)d_in[22];
    const float* b1i    = (const float*)d_in[23];
    const float* W2i    = (const float*)d_in[24];
    const float* b2i    = (const float*)d_in[25];

    float *qkvp, *nrm1p, *attnp, *rp, *lp, *hidp, *op;
    cudaGetSymbolAddress((void**)&qkvp,  g_qkv);
    cudaGetSymbolAddress((void**)&nrm1p, g_nrm1);
    cudaGetSymbolAddress((void**)&attnp, g_attn);
    cudaGetSymbolAddress((void**)&rp,    g_r);
    cudaGetSymbolAddress((void**)&lp,    g_l);
    cudaGetSymbolAddress((void**)&hidp,  g_hid);
    cudaGetSymbolAddress((void**)&op,    g_o);

    float* qkv0  = qkvp;             float* qkv1  = qkvp  + NTOK * 768;
    float* nrm10 = nrm1p;            float* nrm11 = nrm1p + NTOK * EMBD;
    float* attn0 = attnp;            float* attn1 = attnp + NTOK * EMBD;
    float* r0    = rp;               float* r1    = rp    + NTOK * EMBD;
    float* l0    = lp;               float* l1    = lp    + NTOK * EMBD;
    float* hid0  = hidp;             float* hid1  = hidp  + NTOK * HIDD;
    float* o0    = op;               float* o1    = op    + NTOK * EMBD;

    dim3 blk(16, 16);

    // LN1 (residual base)
    ln_kernel<<<dim3(NTOK, 2), 256>>>(vis, ir, ln1v_w, ln1v_b, ln1i_w, ln1i_b,
                                      nrm10, nrm11);

    // QKV projections from RAW embeddings
    sgemm<<<dim3(768 / 32, 7), blk>>>(vis, Wqkv_v, bqkv_v, nullptr, qkv0,
                                      NTOK, 768, EMBD, 0);
    sgemm<<<dim3(768 / 32, 7), blk>>>(ir,  Wqkv_i, bqkv_i, nullptr, qkv1,
                                      NTOK, 768, EMBD, 0);

    // cross attention (both directions)
    attn_kernel<<<dim3(NTOK, NH, 2), 128>>>();

    // output projection + residual (LN1 output)
    sgemm<<<dim3(EMBD / 32, 7), blk>>>(attn0, Wp_v, bp_v, nrm10, r0,
                                       NTOK, EMBD, EMBD, 0);
    sgemm<<<dim3(EMBD / 32, 7), blk>>>(attn1, Wp_i, bp_i, nrm11, r1,
                                       NTOK, EMBD, EMBD, 0);

    // LN2
    ln_kernel<<<dim3(NTOK, 2), 256>>>(r0, r1, ln2v_w, ln2v_b, ln2i_w, ln2i_b,
                                      l0, l1);

    // FF1 + exact GELU
    sgemm<<<dim3(HIDD / 32, 7), blk>>>(l0, W1v, b1v, nullptr, hid0,
                                       NTOK, HIDD, EMBD, 1);
    sgemm<<<dim3(HIDD / 32, 7), blk>>>(l1, W1i, b1i, nullptr, hid1,
                                       NTOK, HIDD, EMBD, 1);

    // FF2 + residual (LN2 output)
    sgemm<<<dim3(EMBD / 32, 7), blk>>>(hid0, W2v, b2v, l0, o0,
                                       NTOK, EMBD, HIDD, 0);
    sgemm<<<dim3(EMBD / 32, 7), blk>>>(hid1, W2i, b2i, l1, o1,
                                       NTOK, EMBD, HIDD, 0);

    // pixel-shuffle recon + concat (ch0 = ir, ch1 = vis)
    recon_kernel<<<(2 * 224 * 224 + 255) / 256, 256>>>((float*)d_out);
}

// round 4
// speedup vs baseline: 2.3074x; 2.3074x over previous
#include <cuda_runtime.h>
#include <math.h>

#define NTOK 196
#define EMBD 256
#define HIDD 1024
#define NH   8
#define DHD  32

// ---------------- scratch (allocation-free: __device__ globals) ----------------
__device__ float g_qkv[2][NTOK * 768];    // per-stream QKV projection (n, (h d 3))
__device__ float g_nrm1[2][NTOK * EMBD];  // LN1 outputs (residual base)
__device__ float g_attn[2][NTOK * EMBD];  // attention output, (n, h*d)
__device__ float g_r[2][NTOK * EMBD];     // residual sum
__device__ float g_l[2][NTOK * EMBD];     // LN2 outputs
__device__ float g_hid[2][NTOK * HIDD];   // FF hidden
__device__ float g_part[8][NTOK * EMBD];  // FF2 split-K partials [ks*2+s]

// ---------------- LayerNorm: one block per (row, stream) ----------------
__global__ void ln_kernel(const float* __restrict__ x0, const float* __restrict__ x1,
                          const float* __restrict__ w0, const float* __restrict__ b0,
                          const float* __restrict__ w1, const float* __restrict__ b1,
                          float* __restrict__ o0, float* __restrict__ o1)
{
    int s = blockIdx.y;
    const float* x = (s ? x1 : x0) + blockIdx.x * EMBD;
    const float* w = s ? w1 : w0;
    const float* b = s ? b1 : b0;
    float* o = (s ? o1 : o0) + blockIdx.x * EMBD;

    int tid = threadIdx.x;          // 256 threads, one element each
    float v = x[tid];

    __shared__ float red[8];
    float t = v;
    #pragma unroll
    for (int off = 16; off; off >>= 1) t += __shfl_xor_sync(0xffffffffu, t, off);
    if ((tid & 31) == 0) red[tid >> 5] = t;
    __syncthreads();
    float mean = (red[0] + red[1] + red[2] + red[3] +
                  red[4] + red[5] + red[6] + red[7]) * (1.0f / EMBD);
    __syncthreads();

    float d = v - mean;
    t = d * d;
    #pragma unroll
    for (int off = 16; off; off >>= 1) t += __shfl_xor_sync(0xffffffffu, t, off);
    if ((tid & 31) == 0) red[tid >> 5] = t;
    __syncthreads();
    float var = (red[0] + red[1] + red[2] + red[3] +
                 red[4] + red[5] + red[6] + red[7]) * (1.0f / EMBD);

    o[tid] = d * rsqrtf(var + 1e-5f) * w[tid] + b[tid];
}

// ---------------- batched 64x64x16 SGEMM, 4x4 microtile, fused epilogue ------
// blockIdx.z: s = z&1 (stream), ks = z>>1 (K-split slice).
// C[z] = act(A[s][M, klen@kstart] @ B[s][klen@kstart, N] + bias[s]) + res[s]
struct GA {
    const float* A[2];
    const float* B[2];
    const float* bias[2];
    const float* res[2];
    float* C[8];
    int M, N, lda, klen, act;
};

__global__ void gemm64(GA ga)
{
    __shared__ float As[16][64];
    __shared__ float Bs[16][64];

    int z = blockIdx.z;
    int s = z & 1;
    int kstart = (z >> 1) * ga.klen;

    const float* A = ga.A[s];
    const float* B = ga.B[s];

    int tid = threadIdx.x;           // 256
    int tx = tid & 15, ty = tid >> 4;
    int row0 = blockIdx.y * 64, col0 = blockIdx.x * 64;

    float acc[4][4] = {};

    int ar = tid >> 2, ak = (tid & 3) * 4;     // A loader: row ar, 4 k's
    int bk = tid >> 4, bn = (tid & 15) * 4;    // B loader: k bk, 4 n's

    for (int k0 = 0; k0 < ga.klen; k0 += 16) {
        float4 av;
        if (row0 + ar < ga.M)
            av = *(const float4*)&A[(row0 + ar) * ga.lda + kstart + k0 + ak];
        else
            av = make_float4(0.f, 0.f, 0.f, 0.f);
        As[ak + 0][ar] = av.x; As[ak + 1][ar] = av.y;
        As[ak + 2][ar] = av.z; As[ak + 3][ar] = av.w;

        *(float4*)&Bs[bk][bn] =
            *(const float4*)&B[(kstart + k0 + bk) * ga.N + col0 + bn];
        __syncthreads();

        #pragma unroll
        for (int k = 0; k < 16; k++) {
            float4 a = *(float4*)&As[k][ty * 4];
            float4 b = *(float4*)&Bs[k][tx * 4];
            acc[0][0] += a.x * b.x; acc[0][1] += a.x * b.y;
            acc[0][2] += a.x * b.z; acc[0][3] += a.x * b.w;
            acc[1][0] += a.y * b.x; acc[1][1] += a.y * b.y;
            acc[1][2] += a.y * b.z; acc[1][3] += a.y * b.w;
            acc[2][0] += a.z * b.x; acc[2][1] += a.z * b.y;
            acc[2][2] += a.z * b.z; acc[2][3] += a.z * b.w;
            acc[3][0] += a.w * b.x; acc[3][1] += a.w * b.y;
            acc[3][2] += a.w * b.z; acc[3][3] += a.w * b.w;
        }
        __syncthreads();
    }

    float* C = ga.C[z];
    const float* bi = ga.bias[s];
    const float* rs = ga.res[s];

    #pragma unroll
    for (int i = 0; i < 4; i++) {
        int r = row0 + ty * 4 + i;
        if (r >= ga.M) break;
        #pragma unroll
        for (int j = 0; j < 4; j++) {
            int c = col0 + tx * 4 + j;
            float v = acc[i][j];
            if (bi) v += bi[c];
            if (ga.act) v = 0.5f * v * (1.0f + erff(v * 0.70710678118654752f));
            if (rs) v += rs[r * ga.N + c];
            C[r * ga.N + c] = v;
        }
    }
}

// ---------------- attention: block per (q-tile, head, out-stream) -------------
// K/V/Q staged in dynamic shared memory once per block; 256 threads.
// smem floats: Ks[32][200] | Vs[196][32] | Ss[32][200] | Qs[32][32] | inv[32]
#define SM_KS 0
#define SM_VS (32 * 200)
#define SM_SS (SM_VS + 196 * 32)
#define SM_QS (SM_SS + 32 * 200)
#define SM_IV (SM_QS + 32 * 32)
#define SM_TOT ((SM_IV + 32) * 4)

__global__ void attn2()
{
    extern __shared__ float buf[];
    float (*Ks)[200] = (float(*)[200])(buf + SM_KS);
    float (*Vs)[32]  = (float(*)[32])(buf + SM_VS);
    float (*Ss)[200] = (float(*)[200])(buf + SM_SS);
    float (*Qs)[32]  = (float(*)[32])(buf + SM_QS);
    float* inv       = buf + SM_IV;

    int qt = blockIdx.x, h = blockIdx.y, s = blockIdx.z;
    const float* qkv_q  = g_qkv[s];
    const float* qkv_kv = g_qkv[1 - s];
    int tid = threadIdx.x;

    // stage K (d-major) and V (j-major)
    for (int idx = tid; idx < NTOK * DHD; idx += 256) {
        int j = idx >> 5, d = idx & 31;
        const float* base = qkv_kv + j * 768 + (h * DHD + d) * 3;
        Ks[d][j] = base[1];
        Vs[j][d] = base[2];
    }
    // stage Q tile
    for (int idx = tid; idx < 32 * 32; idx += 256) {
        int q = idx >> 5, d = idx & 31;
        int qg = qt * 32 + q;
        Qs[q][d] = (qg < NTOK) ? qkv_q[qg * 768 + (h * DHD + d) * 3] : 0.f;
    }
    __syncthreads();

    // scores: thread = (query q, key-group g); each group owns j = g*4 + 32*kk
    {
        int q = tid >> 3, g = tid & 7;
        float qr[32];
        #pragma unroll
        for (int d = 0; d < 32; d++) qr[d] = Qs[q][d];

        #pragma unroll
        for (int kk = 0; kk < 7; kk++) {
            int j0 = g * 4 + kk * 32;
            if (j0 >= NTOK) break;
            float a0 = 0.f, a1 = 0.f, a2 = 0.f, a3 = 0.f;
            #pragma unroll
            for (int d = 0; d < 32; d++) {
                float4 kv = *(float4*)&Ks[d][j0];
                a0 += qr[d] * kv.x; a1 += qr[d] * kv.y;
                a2 += qr[d] * kv.z; a3 += qr[d] * kv.w;
            }
            Ss[q][j0 + 0] = a0 * 0.0625f;
            Ss[q][j0 + 1] = a1 * 0.0625f;
            Ss[q][j0 + 2] = a2 * 0.0625f;
            Ss[q][j0 + 3] = a3 * 0.0625f;
        }
    }
    __syncthreads();

    // softmax: warp w handles rows w*4 .. w*4+3
    {
        int w = tid >> 5, lane = tid & 31;
        for (int r = 0; r < 4; r++) {
            int q = w * 4 + r;
            float m = -1e30f;
            for (int j = lane; j < NTOK; j += 32) m = fmaxf(m, Ss[q][j]);
            #pragma unroll
            for (int off = 16; off; off >>= 1)
                m = fmaxf(m, __shfl_xor_sync(0xffffffffu, m, off));
            float sum = 0.f;
            for (int j = lane; j < NTOK; j += 32) {
                float e = __expf(Ss[q][j] - m);
                Ss[q][j] = e;
                sum += e;
            }
            #pragma unroll
            for (int off = 16; off; off >>= 1)
                sum += __shfl_xor_sync(0xffffffffu, sum, off);
            if (lane == 0) inv[q] = 1.0f / sum;
        }
    }
    __syncthreads();

    // PV: thread = (q, 4 d's)
    {
        int q = tid >> 3, d0 = (tid & 7) * 4;
        float4 acc = make_float4(0.f, 0.f, 0.f, 0.f);
        for (int j = 0; j < NTOK; j += 2) {
            float p0 = Ss[q][j], p1 = Ss[q][j + 1];
            float4 v0 = *(float4*)&Vs[j][d0];
            float4 v1 = *(float4*)&Vs[j + 1][d0];
            acc.x += p0 * v0.x + p1 * v1.x;
            acc.y += p0 * v0.y + p1 * v1.y;
            acc.z += p0 * v0.z + p1 * v1.z;
            acc.w += p0 * v0.w + p1 * v1.w;
        }
        float iv = inv[q];
        acc.x *= iv; acc.y *= iv; acc.z *= iv; acc.w *= iv;
        int qg = qt * 32 + q;
        if (qg < NTOK)
            *(float4*)&g_attn[s][qg * EMBD + h * DHD + d0] = acc;
    }
}

// ---------------- FF2 reduce + bias + residual + pixel-shuffle store ----------
// out (1,2,224,224): ch0 = ir path (stream 1), ch1 = vis path (stream 0)
__global__ void ff2_reduce(const float* __restrict__ b2v,
                           const float* __restrict__ b2i,
                           float* __restrict__ out)
{
    int t = blockIdx.x * 256 + threadIdx.x;
    if (t >= 2 * NTOK * EMBD) return;
    int s = t / (NTOK * EMBD);
    int rem = t % (NTOK * EMBD);
    int n = rem >> 8, e = rem & 255;

    float v = g_part[0 * 2 + s][rem] + g_part[1 * 2 + s][rem] +
              g_part[2 * 2 + s][rem] + g_part[3 * 2 + s][rem];
    v += (s ? b2i : b2v)[e];
    v += g_l[s][rem];

    int i = n / 14, j = n % 14;
    int p = e >> 4, q = e & 15;
    int ch = s ? 0 : 1;
    out[ch * 50176 + p * 3136 + q * 196 + i * 14 + j] = v;
}

// ---------------- launch ----------------
extern "C" void kernel_launch(void* const* d_in, const int* in_sizes, int n_in,
                              void* d_out, int out_size)
{
    const float* vis    = (const float*)d_in[0];
    const float* ir     = (const float*)d_in[1];
    const float* ln1v_w = (const float*)d_in[2];
    const float* ln1v_b = (const float*)d_in[3];
    const float* ln1i_w = (const float*)d_in[4];
    const float* ln1i_b = (const float*)d_in[5];
    const float* ln2v_w = (const float*)d_in[6];
    const float* ln2v_b = (const float*)d_in[7];
    const float* ln2i_w = (const float*)d_in[8];
    const float* ln2i_b = (const float*)d_in[9];
    const float* Wqkv_v = (const float*)d_in[10];
    const float* bqkv_v = (const float*)d_in[11];
    const float* Wqkv_i = (const float*)d_in[12];
    const float* bqkv_i = (const float*)d_in[13];
    const float* Wp_v   = (const float*)d_in[14];
    const float* bp_v   = (const float*)d_in[15];
    const float* Wp_i   = (const float*)d_in[16];
    const float* bp_i   = (const float*)d_in[17];
    const float* W1v    = (const float*)d_in[18];
    const float* b1v    = (const float*)d_in[19];
    const float* W2v    = (const float*)d_in[20];
    const float* b2v    = (const float*)d_in[21];
    const float* W1i    = (const float*)d_in[22];
    const float* b1i    = (const float*)d_in[23];
    const float* W2i    = (const float*)d_in[24];
    const float* b2i    = (const float*)d_in[25];

    float *qkvp, *nrm1p, *attnp, *rp, *lp, *hidp, *partp;
    cudaGetSymbolAddress((void**)&qkvp,  g_qkv);
    cudaGetSymbolAddress((void**)&nrm1p, g_nrm1);
    cudaGetSymbolAddress((void**)&attnp, g_attn);
    cudaGetSymbolAddress((void**)&rp,    g_r);
    cudaGetSymbolAddress((void**)&lp,    g_l);
    cudaGetSymbolAddress((void**)&hidp,  g_hid);
    cudaGetSymbolAddress((void**)&partp, g_part);

    float* qkv0  = qkvp;   float* qkv1  = qkvp  + NTOK * 768;
    float* nrm10 = nrm1p;  float* nrm11 = nrm1p + NTOK * EMBD;
    float* attn0 = attnp;  float* attn1 = attnp + NTOK * EMBD;
    float* r0    = rp;     float* r1    = rp    + NTOK * EMBD;
    float* l0    = lp;     float* l1    = lp    + NTOK * EMBD;
    float* hid0  = hidp;   float* hid1  = hidp  + NTOK * HIDD;

    cudaFuncSetAttribute(attn2, cudaFuncAttributeMaxDynamicSharedMemorySize, SM_TOT);

    // LN1 (residual base)
    ln_kernel<<<dim3(NTOK, 2), 256>>>(vis, ir, ln1v_w, ln1v_b, ln1i_w, ln1i_b,
                                      nrm10, nrm11);

    // QKV projections from RAW embeddings (both streams)
    {
        GA ga = {};
        ga.A[0] = vis;    ga.A[1] = ir;
        ga.B[0] = Wqkv_v; ga.B[1] = Wqkv_i;
        ga.bias[0] = bqkv_v; ga.bias[1] = bqkv_i;
        ga.C[0] = qkv0; ga.C[1] = qkv1;
        ga.M = NTOK; ga.N = 768; ga.lda = EMBD; ga.klen = EMBD; ga.act = 0;
        gemm64<<<dim3(768 / 64, 4, 2), 256>>>(ga);
    }

    // cross attention (both directions)
    attn2<<<dim3(7, NH, 2), 256, SM_TOT>>>();

    // output projection + residual (LN1 output)
    {
        GA ga = {};
        ga.A[0] = attn0; ga.A[1] = attn1;
        ga.B[0] = Wp_v;  ga.B[1] = Wp_i;
        ga.bias[0] = bp_v;  ga.bias[1] = bp_i;
        ga.res[0] = nrm10;  ga.res[1] = nrm11;
        ga.C[0] = r0; ga.C[1] = r1;
        ga.M = NTOK; ga.N = EMBD; ga.lda = EMBD; ga.klen = EMBD; ga.act = 0;
        gemm64<<<dim3(EMBD / 64, 4, 2), 256>>>(ga);
    }

    // LN2
    ln_kernel<<<dim3(NTOK, 2), 256>>>(r0, r1, ln2v_w, ln2v_b, ln2i_w, ln2i_b,
                                      l0, l1);

    // FF1 + exact GELU
    {
        GA ga = {};
        ga.A[0] = l0;  ga.A[1] = l1;
        ga.B[0] = W1v; ga.B[1] = W1i;
        ga.bias[0] = b1v; ga.bias[1] = b1i;
        ga.C[0] = hid0; ga.C[1] = hid1;
        ga.M = NTOK; ga.N = HIDD; ga.lda = EMBD; ga.klen = EMBD; ga.act = 1;
        gemm64<<<dim3(HIDD / 64, 4, 2), 256>>>(ga);
    }

    // FF2 split-K=4 partials (raw accum, no bias/res)
    {
        GA ga = {};
        ga.A[0] = hid0; ga.A[1] = hid1;
        ga.B[0] = W2v;  ga.B[1] = W2i;
        for (int z = 0; z < 8; z++) ga.C[z] = partp + z * (NTOK * EMBD);
        ga.M = NTOK; ga.N = EMBD; ga.lda = HIDD; ga.klen = HIDD / 4; ga.act = 0;
        gemm64<<<dim3(EMBD / 64, 4, 8), 256>>>(ga);
    }

    // reduce + bias + residual + pixel-shuffle recon into d_out
    ff2_reduce<<<(2 * NTOK * EMBD + 255) / 256, 256>>>(b2v, b2i, (float*)d_out);
}

// round 5
// speedup vs baseline: 3.2228x; 1.3967x over previous
#include <cuda_runtime.h>
#include <math.h>

#define NTOK 196
#define EMBD 256
#define HIDD 1024
#define NH   8
#define DHD  32
#define NB   296
#define NTHR 256

// ---------------- scratch (allocation-free: __device__ globals) ----------------
__device__ float g_part[16][NTOK * HIDD]; // split-K partials, reused per stage
__device__ float g_nrm1[2][NTOK * EMBD];  // LN1 outputs (residual base)
__device__ float g_q[2][NH][NTOK * DHD];  // deinterleaved Q  [n][d]
__device__ float g_k[2][NH][DHD * 200];   // deinterleaved K  [d][n] (pad 200)
__device__ float g_v[2][NH][NTOK * DHD];  // deinterleaved V  [n][d]
__device__ float g_attn[2][NTOK * EMBD];  // attention output
__device__ float g_l[2][NTOK * EMBD];     // LN2 outputs
__device__ float g_hid[2][NTOK * HIDD];   // FF hidden (post-GELU)
__device__ unsigned g_count = 0;
__device__ unsigned g_gen = 0;

// ---------------- grid-wide barrier (all NB blocks co-resident) ----------------
__device__ __forceinline__ void gsync()
{
    __syncthreads();
    if (threadIdx.x == 0) {
        __threadfence();
        unsigned gen = *(volatile unsigned*)&g_gen;
        if (atomicAdd(&g_count, 1u) == NB - 1u) {
            g_count = 0u;
            __threadfence();
            atomicAdd(&g_gen, 1u);
        } else {
            while (*(volatile unsigned*)&g_gen == gen) __nanosleep(64);
        }
        __threadfence();
    }
    __syncthreads();
}

// ---------------- packed fp32x2 FMA helpers ----------------
__device__ __forceinline__ void ffma2(unsigned long long& acc,
                                      unsigned long long a, unsigned long long b)
{
    asm("fma.rn.f32x2 %0, %1, %2, %0;" : "+l"(acc) : "l"(a), "l"(b));
}
__device__ __forceinline__ unsigned long long pk2(float x, float y)
{
    unsigned long long r;
    asm("mov.b64 %0, {%1, %2};" : "=l"(r) : "f"(x), "f"(y));
    return r;
}
__device__ __forceinline__ float2 up2(unsigned long long v)
{
    float2 r;
    asm("mov.b64 {%0, %1}, %2;" : "=f"(r.x), "=f"(r.y) : "l"(v));
    return r;
}

// ---------------- 64x128 GEMM tile, 4x8 microtile, f32x2 accum ----------------
// Cp[row0.., col0..] = A[M x K slice] @ B[K x N]; partial (no bias/act).
__device__ void gemm_tile(const float* __restrict__ A, int lda, int M,
                          const float* __restrict__ B, int ldb,
                          float* __restrict__ Cp, int ldc,
                          int row0, int col0, int kstart, int klen, float* sm)
{
    float (*As)[68]  = (float(*)[68])sm;            // [16][68] padded
    float* Bs = sm + 16 * 68;                        // [16][128] flat

    int tid = threadIdx.x;
    int tx = tid & 15, ty = tid >> 4;

    unsigned long long acc[4][4];
    #pragma unroll
    for (int i = 0; i < 4; i++)
        #pragma unroll
        for (int j = 0; j < 4; j++) acc[i][j] = 0ull;

    int ar = tid >> 2, ak = (tid & 3) * 4;           // A loader
    bool avalid = (row0 + ar) < M;
    const float* Arow = A + (row0 + ar) * lda + kstart + ak;
    int brow = tid >> 5, bcol = (tid * 4) & 127;     // B loader: flat tid*4

    for (int k0 = 0; k0 < klen; k0 += 16) {
        float4 av = make_float4(0.f, 0.f, 0.f, 0.f);
        if (avalid) av = *(const float4*)(Arow + k0);
        As[ak + 0][ar] = av.x; As[ak + 1][ar] = av.y;
        As[ak + 2][ar] = av.z; As[ak + 3][ar] = av.w;

        const float* Bb = B + (kstart + k0) * ldb + col0;
        *(float4*)&Bs[brow * 128 + bcol] =
            *(const float4*)&Bb[brow * ldb + bcol];
        *(float4*)&Bs[(brow + 8) * 128 + bcol] =
            *(const float4*)&Bb[(brow + 8) * ldb + bcol];
        __syncthreads();

        #pragma unroll
        for (int k = 0; k < 16; k++) {
            float4 a = *(float4*)&As[k][ty * 4];
            ulonglong2 b01 = *(ulonglong2*)&Bs[k * 128 + tx * 8];
            ulonglong2 b23 = *(ulonglong2*)&Bs[k * 128 + tx * 8 + 4];
            unsigned long long a0 = pk2(a.x, a.x), a1 = pk2(a.y, a.y);
            unsigned long long a2 = pk2(a.z, a.z), a3 = pk2(a.w, a.w);
            ffma2(acc[0][0], a0, b01.x); ffma2(acc[0][1], a0, b01.y);
            ffma2(acc[0][2], a0, b23.x); ffma2(acc[0][3], a0, b23.y);
            ffma2(acc[1][0], a1, b01.x); ffma2(acc[1][1], a1, b01.y);
            ffma2(acc[1][2], a1, b23.x); ffma2(acc[1][3], a1, b23.y);
            ffma2(acc[2][0], a2, b01.x); ffma2(acc[2][1], a2, b01.y);
            ffma2(acc[2][2], a2, b23.x); ffma2(acc[2][3], a2, b23.y);
            ffma2(acc[3][0], a3, b01.x); ffma2(acc[3][1], a3, b01.y);
            ffma2(acc[3][2], a3, b23.x); ffma2(acc[3][3], a3, b23.y);
        }
        __syncthreads();
    }

    #pragma unroll
    for (int i = 0; i < 4; i++) {
        int r = row0 + ty * 4 + i;
        if (r < M) {
            float2 v0 = up2(acc[i][0]), v1 = up2(acc[i][1]);
            float2 v2 = up2(acc[i][2]), v3 = up2(acc[i][3]);
            float4 w0 = make_float4(v0.x, v0.y, v1.x, v1.y);
            float4 w1 = make_float4(v2.x, v2.y, v3.x, v3.y);
            *(float4*)&Cp[r * ldc + col0 + tx * 8]     = w0;
            *(float4*)&Cp[r * ldc + col0 + tx * 8 + 4] = w1;
        }
    }
}

// ---------------- block LayerNorm over 256-elem row (256 threads) -------------
__device__ __forceinline__ float ln_norm(float v, float w, float b, float* red)
{
    int tid = threadIdx.x;
    float t = v;
    #pragma unroll
    for (int off = 16; off; off >>= 1) t += __shfl_xor_sync(0xffffffffu, t, off);
    __syncthreads();
    if ((tid & 31) == 0) red[tid >> 5] = t;
    __syncthreads();
    float mean = (red[0] + red[1] + red[2] + red[3] +
                  red[4] + red[5] + red[6] + red[7]) * (1.0f / EMBD);
    float d = v - mean;
    t = d * d;
    #pragma unroll
    for (int off = 16; off; off >>= 1) t += __shfl_xor_sync(0xffffffffu, t, off);
    __syncthreads();
    if ((tid & 31) == 0) red[tid >> 5] = t;
    __syncthreads();
    float var = (red[0] + red[1] + red[2] + red[3] +
                 red[4] + red[5] + red[6] + red[7]) * (1.0f / EMBD);
    return d * rsqrtf(var + 1e-5f) * w + b;
}

// ---------------- attention smem layout (floats) ----------------
#define A_KS 0
#define A_VS (32 * 200)
#define A_SS (A_VS + NTOK * DHD)
#define A_QS (A_SS + 32 * 200)
#define A_IV (A_QS + 32 * 32)
#define SMEM_FLOATS (A_IV + 32)
#define SMEM_BYTES  (SMEM_FLOATS * 4)

__device__ void attn_tile(int qt, int h, int s, float* buf)
{
    float (*Ks)[200] = (float(*)[200])(buf + A_KS);
    float (*Vs)[DHD] = (float(*)[DHD])(buf + A_VS);
    float (*Ss)[200] = (float(*)[200])(buf + A_SS);
    float (*Qs)[DHD] = (float(*)[DHD])(buf + A_QS);
    float* inv = buf + A_IV;
    int tid = threadIdx.x;

    const float* gk = g_k[1 - s][h];
    const float* gv = g_v[1 - s][h];
    const float* gq = g_q[s][h];

    for (int i = tid; i < 32 * 50; i += NTHR)
        ((float4*)(buf + A_KS))[i] = ((const float4*)gk)[i];
    for (int i = tid; i < NTOK * 8; i += NTHR)
        ((float4*)(buf + A_VS))[i] = ((const float4*)gv)[i];
    for (int i = tid; i < 32 * 8; i += NTHR) {
        int q = i >> 3, d4 = (i & 7) << 2;
        int qg = qt * 32 + q;
        float4 v = make_float4(0.f, 0.f, 0.f, 0.f);
        if (qg < NTOK) v = *(const float4*)&gq[qg * DHD + d4];
        *(float4*)&Qs[q][d4] = v;
    }
    __syncthreads();

    // scores
    {
        int q = tid >> 3, g = tid & 7;
        float qr[32];
        #pragma unroll
        for (int d = 0; d < 32; d++) qr[d] = Qs[q][d];
        #pragma unroll
        for (int kk = 0; kk < 7; kk++) {
            int j0 = g * 4 + kk * 32;
            if (j0 >= NTOK) break;
            float a0 = 0.f, a1 = 0.f, a2 = 0.f, a3 = 0.f;
            #pragma unroll
            for (int d = 0; d < 32; d++) {
                float4 kv = *(float4*)&Ks[d][j0];
                a0 += qr[d] * kv.x; a1 += qr[d] * kv.y;
                a2 += qr[d] * kv.z; a3 += qr[d] * kv.w;
            }
            Ss[q][j0 + 0] = a0 * 0.0625f;
            Ss[q][j0 + 1] = a1 * 0.0625f;
            Ss[q][j0 + 2] = a2 * 0.0625f;
            Ss[q][j0 + 3] = a3 * 0.0625f;
        }
    }
    __syncthreads();

    // softmax
    {
        int w = tid >> 5, lane = tid & 31;
        for (int r = 0; r < 4; r++) {
            int q = w * 4 + r;
            float m = -1e30f;
            for (int j = lane; j < NTOK; j += 32) m = fmaxf(m, Ss[q][j]);
            #pragma unroll
            for (int off = 16; off; off >>= 1)
                m = fmaxf(m, __shfl_xor_sync(0xffffffffu, m, off));
            float sum = 0.f;
            for (int j = lane; j < NTOK; j += 32) {
                float e = __expf(Ss[q][j] - m);
                Ss[q][j] = e;
                sum += e;
            }
            #pragma unroll
            for (int off = 16; off; off >>= 1)
                sum += __shfl_xor_sync(0xffffffffu, sum, off);
            if (lane == 0) inv[q] = 1.0f / sum;
        }
    }
    __syncthreads();

    // PV
    {
        int q = tid >> 3, d0 = (tid & 7) * 4;
        float4 acc = make_float4(0.f, 0.f, 0.f, 0.f);
        for (int j = 0; j < NTOK; j += 2) {
            float p0 = Ss[q][j], p1 = Ss[q][j + 1];
            float4 v0 = *(float4*)&Vs[j][d0];
            float4 v1 = *(float4*)&Vs[j + 1][d0];
            acc.x += p0 * v0.x + p1 * v1.x;
            acc.y += p0 * v0.y + p1 * v1.y;
            acc.z += p0 * v0.z + p1 * v1.z;
            acc.w += p0 * v0.w + p1 * v1.w;
        }
        float iv = inv[q];
        acc.x *= iv; acc.y *= iv; acc.z *= iv; acc.w *= iv;
        int qg = qt * 32 + q;
        if (qg < NTOK)
            *(float4*)&g_attn[s][qg * EMBD + h * DHD + d0] = acc;
    }
}

// ---------------- fused persistent kernel ----------------
struct Params {
    const float *vis, *ir;
    const float *ln1w[2], *ln1b[2], *ln2w[2], *ln2b[2];
    const float *Wqkv[2], *bqkv[2], *Wp[2], *bp[2];
    const float *W1[2], *b1[2], *W2[2], *b2[2];
    float* out;
};

__global__ void __launch_bounds__(NTHR, 2) fused(Params p)
{
    extern __shared__ float sm[];
    int b = blockIdx.x;
    int tid = threadIdx.x;

    // ---- S0: QKV split-K=2 partial GEMMs (96 items) + LN1 (rest) ----
    if (b < 96) {
        int t = b;
        int nt = t % 6; t /= 6;
        int mt = t % 4; t /= 4;
        int s = t & 1, ks = t >> 1;
        gemm_tile(s ? p.ir : p.vis, EMBD, NTOK, p.Wqkv[s], 768,
                  g_part[ks * 2 + s], 768, mt * 64, nt * 128, ks * 128, 128, sm);
    } else {
        for (int r = b - 96; r < 2 * NTOK; r += NB - 96) {
            int s = r >= NTOK;
            int n = s ? r - NTOK : r;
            float v = (s ? p.ir : p.vis)[n * EMBD + tid];
            g_nrm1[s][n * EMBD + tid] =
                ln_norm(v, p.ln1w[s][tid], p.ln1b[s][tid], sm);
        }
    }
    gsync();

    // ---- S0.5: QKV reduce + bias + deinterleave ----
    {
        int tot = 2 * NTOK * 768;
        for (int e = b * NTHR + tid; e < tot; e += NB * NTHR) {
            int s = e / (NTOK * 768);
            int rem = e - s * (NTOK * 768);
            int n = rem / 768, c = rem - n * 768;
            float v = g_part[s][rem] + g_part[2 + s][rem] + p.bqkv[s][c];
            int hd = c / 3, t3 = c - hd * 3;
            int h = hd >> 5, d = hd & 31;
            if (t3 == 0)      g_q[s][h][n * DHD + d] = v;
            else if (t3 == 1) g_k[s][h][d * 200 + n] = v;
            else              g_v[s][h][n * DHD + d] = v;
        }
    }
    gsync();

    // ---- S1: cross attention (112 items) ----
    if (b < 112) {
        int t = b;
        int qt = t % 7; t /= 7;
        int h = t % 8;
        int s = t / 8;
        attn_tile(qt, h, s, sm);
    }
    gsync();

    // ---- S2: proj split-K=4 partial GEMMs (64 items) ----
    if (b < 64) {
        int t = b;
        int nt = t & 1; t >>= 1;
        int mt = t & 3; t >>= 2;
        int s = t & 1, ks = t >> 1;
        gemm_tile(g_attn[s], EMBD, NTOK, p.Wp[s], EMBD,
                  g_part[ks * 2 + s], EMBD, mt * 64, nt * 128, ks * 64, 64, sm);
    }
    gsync();

    // ---- S3: proj reduce + bias + residual + LN2 ----
    for (int r = b; r < 2 * NTOK; r += NB) {
        int s = r >= NTOK;
        int n = s ? r - NTOK : r;
        int idx = n * EMBD + tid;
        float v = g_part[s][idx] + g_part[2 + s][idx] +
                  g_part[4 + s][idx] + g_part[6 + s][idx] +
                  p.bp[s][tid] + g_nrm1[s][idx];
        g_l[s][idx] = ln_norm(v, p.ln2w[s][tid], p.ln2b[s][tid], sm);
    }
    gsync();

    // ---- S4: FF1 split-K=2 partial GEMMs (128 items) ----
    if (b < 128) {
        int t = b;
        int nt = t & 7; t >>= 3;
        int mt = t & 3; t >>= 2;
        int s = t & 1, ks = t >> 1;
        gemm_tile(g_l[s], EMBD, NTOK, p.W1[s], HIDD,
                  g_part[ks * 2 + s], HIDD, mt * 64, nt * 128, ks * 128, 128, sm);
    }
    gsync();

    // ---- S4.5: FF1 reduce + bias + exact GELU ----
    {
        int tot = 2 * NTOK * HIDD;
        for (int e = b * NTHR + tid; e < tot; e += NB * NTHR) {
            int s = e / (NTOK * HIDD);
            int rem = e - s * (NTOK * HIDD);
            int c = rem & 1023;
            float v = g_part[s][rem] + g_part[2 + s][rem] + p.b1[s][c];
            v = 0.5f * v * (1.0f + erff(v * 0.70710678118654752f));
            g_hid[s][rem] = v;
        }
    }
    gsync();

    // ---- S5: FF2 split-K=8 partial GEMMs (128 items) ----
    if (b < 128) {
        int t = b;
        int nt = t & 1; t >>= 1;
        int mt = t & 3; t >>= 2;
        int s = t & 1, ks = t >> 1;      // ks 0..7
        gemm_tile(g_hid[s], HIDD, NTOK, p.W2[s], EMBD,
                  g_part[ks * 2 + s], EMBD, mt * 64, nt * 128, ks * 128, 128, sm);
    }
    gsync();

    // ---- S6: FF2 reduce + bias + residual + pixel-shuffle to d_out ----
    for (int r = b; r < 2 * NTOK; r += NB) {
        int s = r >= NTOK;
        int n = s ? r - NTOK : r;
        int idx = n * EMBD + tid;
        float v = 0.f;
        #pragma unroll
        for (int ks = 0; ks < 8; ks++) v += g_part[ks * 2 + s][idx];
        v += p.b2[s][tid] + g_l[s][idx];
        int i = n / 14, j = n % 14;
        int pp = tid >> 4, q = tid & 15;
        int ch = s ? 0 : 1;
        p.out[ch * 50176 + pp * 3136 + q * 196 + i * 14 + j] = v;
    }
}

// ---------------- launch ----------------
extern "C" void kernel_launch(void* const* d_in, const int* in_sizes, int n_in,
                              void* d_out, int out_size)
{
    Params pr;
    pr.vis = (const float*)d_in[0];
    pr.ir  = (const float*)d_in[1];
    pr.ln1w[0] = (const float*)d_in[2];  pr.ln1b[0] = (const float*)d_in[3];
    pr.ln1w[1] = (const float*)d_in[4];  pr.ln1b[1] = (const float*)d_in[5];
    pr.ln2w[0] = (const float*)d_in[6];  pr.ln2b[0] = (const float*)d_in[7];
    pr.ln2w[1] = (const float*)d_in[8];  pr.ln2b[1] = (const float*)d_in[9];
    pr.Wqkv[0] = (const float*)d_in[10]; pr.bqkv[0] = (const float*)d_in[11];
    pr.Wqkv[1] = (const float*)d_in[12]; pr.bqkv[1] = (const float*)d_in[13];
    pr.Wp[0]   = (const float*)d_in[14]; pr.bp[0]   = (const float*)d_in[15];
    pr.Wp[1]   = (const float*)d_in[16]; pr.bp[1]   = (const float*)d_in[17];
    pr.W1[0]   = (const float*)d_in[18]; pr.b1[0]   = (const float*)d_in[19];
    pr.W2[0]   = (const float*)d_in[20]; pr.b2[0]   = (const float*)d_in[21];
    pr.W1[1]   = (const float*)d_in[22]; pr.b1[1]   = (const float*)d_in[23];
    pr.W2[1]   = (const float*)d_in[24]; pr.b2[1]   = (const float*)d_in[25];
    pr.out = (float*)d_out;

    cudaFuncSetAttribute(fused, cudaFuncAttributeMaxDynamicSharedMemorySize,
                         SMEM_BYTES);
    fused<<<NB, NTHR, SMEM_BYTES>>>(pr);
}